// round 1
// baseline (speedup 1.0000x reference)
#include <cuda_runtime.h>
#include <math.h>

#define B_GRAPHS 512
#define N_NODES  128
#define F_OUT    256           // HEADS*HID
#define HEADS    4
#define HID      64
#define M_TOT    (B_GRAPHS * N_NODES)   // 65536

// Scratch (static device allocations; harness forbids cudaMalloc)
__device__ float g_H[(size_t)M_TOT * F_OUT];   // post-GEMM features, 64 MiB
__device__ float g_X[(size_t)M_TOT * F_OUT];   // layer activations,  64 MiB
__device__ float g_S[(size_t)M_TOT * HEADS];   // a_src per (node, head)
__device__ float g_D[(size_t)M_TOT * HEADS];   // a_dst per (node, head)

// ---------------------------------------------------------------------------
// GEMM: C[M,256] = A[M,K] @ W[K,256], fp32. BM=128, BN=64, BK=16, 256 thr,
// 8x4 micro-tile per thread.
// ---------------------------------------------------------------------------
__global__ __launch_bounds__(256) void gemm_kernel(
    const float* __restrict__ A, const float* __restrict__ W,
    float* __restrict__ C, int K)
{
    __shared__ float As[16][128];
    __shared__ float Bs[16][64];

    const int tid = threadIdx.x;
    const int m0 = blockIdx.x * 128;
    const int n0 = blockIdx.y * 64;

    const int ty = tid >> 4;         // 0..15 -> 8 rows each
    const int tx = tid & 15;         // 0..15 -> 4 cols each

    // A tile load mapping: 128x16, 2 float4 per thread
    const int a_m = tid >> 2;        // 0..63
    const int a_k = (tid & 3) << 2;  // 0,4,8,12
    // B tile load mapping: 16x64, 1 float4 per thread
    const int b_k = tid >> 4;        // 0..15
    const int b_n = (tid & 15) << 2;

    float acc[8][4];
#pragma unroll
    for (int r = 0; r < 8; r++)
#pragma unroll
        for (int c = 0; c < 4; c++) acc[r][c] = 0.f;

    for (int k0 = 0; k0 < K; k0 += 16) {
        float4 av0 = *(const float4*)&A[(size_t)(m0 + a_m) * K + k0 + a_k];
        float4 av1 = *(const float4*)&A[(size_t)(m0 + a_m + 64) * K + k0 + a_k];
        As[a_k + 0][a_m] = av0.x;  As[a_k + 1][a_m] = av0.y;
        As[a_k + 2][a_m] = av0.z;  As[a_k + 3][a_m] = av0.w;
        As[a_k + 0][a_m + 64] = av1.x;  As[a_k + 1][a_m + 64] = av1.y;
        As[a_k + 2][a_m + 64] = av1.z;  As[a_k + 3][a_m + 64] = av1.w;
        *(float4*)&Bs[b_k][b_n] =
            *(const float4*)&W[(size_t)(k0 + b_k) * 256 + n0 + b_n];
        __syncthreads();

#pragma unroll
        for (int kk = 0; kk < 16; kk++) {
            float a[8], bb[4];
            *(float4*)&a[0] = *(const float4*)&As[kk][ty * 8];
            *(float4*)&a[4] = *(const float4*)&As[kk][ty * 8 + 4];
            *(float4*)&bb[0] = *(const float4*)&Bs[kk][tx * 4];
#pragma unroll
            for (int r = 0; r < 8; r++)
#pragma unroll
                for (int c = 0; c < 4; c++)
                    acc[r][c] = fmaf(a[r], bb[c], acc[r][c]);
        }
        __syncthreads();
    }

#pragma unroll
    for (int r = 0; r < 8; r++) {
        float4 o = make_float4(acc[r][0], acc[r][1], acc[r][2], acc[r][3]);
        *(float4*)&C[(size_t)(m0 + ty * 8 + r) * 256 + n0 + tx * 4] = o;
    }
}

// ---------------------------------------------------------------------------
// Scores: s[n,h] = dot(H[n, 64h:64h+64], att_src[h]); d likewise.
// One warp per node; lane holds 8 contiguous channels (head = lane/8).
// ---------------------------------------------------------------------------
__global__ __launch_bounds__(256) void scores_kernel(
    const float* __restrict__ H, const float* __restrict__ att_src,
    const float* __restrict__ att_dst,
    float* __restrict__ S, float* __restrict__ D)
{
    __shared__ float as_s[256], as_d[256];
    const int tid = threadIdx.x;
    as_s[tid] = att_src[tid];
    as_d[tid] = att_dst[tid];
    __syncthreads();

    const int warp = tid >> 5, lane = tid & 31;
    const int node = blockIdx.x * 8 + warp;
    const int head = lane >> 3;
    const int seg  = lane & 7;

    const float* row = H + (size_t)node * 256 + lane * 8;
    float ps = 0.f, pd = 0.f;
#pragma unroll
    for (int k = 0; k < 8; k++) {
        float x = row[k];
        ps = fmaf(x, as_s[head * 64 + seg * 8 + k], ps);
        pd = fmaf(x, as_d[head * 64 + seg * 8 + k], pd);
    }
#pragma unroll
    for (int off = 4; off; off >>= 1) {
        ps += __shfl_xor_sync(0xffffffffu, ps, off);
        pd += __shfl_xor_sync(0xffffffffu, pd, off);
    }
    if (seg == 0) {
        S[(size_t)node * 4 + head] = ps;
        D[(size_t)node * 4 + head] = pd;
    }
}

// ---------------------------------------------------------------------------
// Attention: one CTA per (b, h). Builds P = softmax_j(leaky(s_j + d_i)) in
// SMEM, then OUT[i, :] = P[i, :] @ Hs + bias.
// ---------------------------------------------------------------------------
#define ATTN_SMEM ((128 * 64 + 128 * 128 + 256) * 4)

__global__ __launch_bounds__(256) void attn_kernel(
    const float* __restrict__ H, const float* __restrict__ S,
    const float* __restrict__ D, const float* __restrict__ bias,
    float* __restrict__ OUT)
{
    extern __shared__ float sm[];
    float* Hs = sm;                 // [128][64]
    float* P  = sm + 128 * 64;      // [128][128]
    float* sv = P + 128 * 128;      // [128]
    float* dv = sv + 128;           // [128]

    const int b = blockIdx.x, h = blockIdx.y;
    const int tid = threadIdx.x, lane = tid & 31, warp = tid >> 5;

    // Load H tile for this (b, h): 128 nodes x 64 channels
    const float* Hb = H + (size_t)b * 128 * 256 + h * 64;
    for (int idx = tid; idx < 128 * 16; idx += 256) {
        int j = idx >> 4, c4 = (idx & 15) << 2;
        *(float4*)&Hs[j * 64 + c4] = *(const float4*)&Hb[(size_t)j * 256 + c4];
    }
    if (tid < 128) sv[tid] = S[((size_t)b * 128 + tid) * 4 + h];
    else { int t = tid - 128; dv[t] = D[((size_t)b * 128 + t) * 4 + h]; }
    __syncthreads();

    // Phase 1: P rows (16 rows per warp)
#pragma unroll 1
    for (int r = 0; r < 16; r++) {
        int i = warp * 16 + r;
        float di = dv[i];
        float v[4];
        float m = -1e30f;
#pragma unroll
        for (int q = 0; q < 4; q++) {
            float a = sv[lane + q * 32] + di;
            v[q] = (a >= 0.f) ? a : 0.2f * a;   // leaky relu, slope 0.2
            m = fmaxf(m, v[q]);
        }
#pragma unroll
        for (int off = 16; off; off >>= 1)
            m = fmaxf(m, __shfl_xor_sync(0xffffffffu, m, off));
        float sum = 0.f;
#pragma unroll
        for (int q = 0; q < 4; q++) { v[q] = __expf(v[q] - m); sum += v[q]; }
#pragma unroll
        for (int off = 16; off; off >>= 1)
            sum += __shfl_xor_sync(0xffffffffu, sum, off);
        float inv = 1.0f / sum;
#pragma unroll
        for (int q = 0; q < 4; q++) P[i * 128 + lane + q * 32] = v[q] * inv;
    }
    __syncthreads();

    // Phase 2: OUT[i, c] = sum_j P[i][j] * Hs[j][c]
    // Each warp: 16 rows; each lane: cols {lane, lane+32}.
    float acc0[16], acc1[16];
#pragma unroll
    for (int r = 0; r < 16; r++) { acc0[r] = 0.f; acc1[r] = 0.f; }

    for (int j = 0; j < 128; j += 2) {
        float h00 = Hs[j * 64 + lane];
        float h01 = Hs[(j + 1) * 64 + lane];
        float h10 = Hs[j * 64 + lane + 32];
        float h11 = Hs[(j + 1) * 64 + lane + 32];
#pragma unroll
        for (int r = 0; r < 16; r++) {
            float2 p = *(const float2*)&P[(warp * 16 + r) * 128 + j];
            acc0[r] = fmaf(p.x, h00, acc0[r]);
            acc0[r] = fmaf(p.y, h01, acc0[r]);
            acc1[r] = fmaf(p.x, h10, acc1[r]);
            acc1[r] = fmaf(p.y, h11, acc1[r]);
        }
    }

    const float bias0 = bias[h * 64 + lane];
    const float bias1 = bias[h * 64 + lane + 32];
#pragma unroll
    for (int r = 0; r < 16; r++) {
        int i = warp * 16 + r;
        float* o = OUT + ((size_t)b * 128 + i) * 256 + h * 64;
        o[lane]      = acc0[r] + bias0;
        o[lane + 32] = acc1[r] + bias1;
    }
}

// ---------------------------------------------------------------------------
// Final reduction: out[b, f] = sum_i X[b, i, f]
// ---------------------------------------------------------------------------
__global__ __launch_bounds__(256) void reduce_kernel(
    const float* __restrict__ X, float* __restrict__ out)
{
    const int b = blockIdx.x, f = threadIdx.x;
    const float* p = X + (size_t)b * 128 * 256 + f;
    float s = 0.f;
#pragma unroll 8
    for (int i = 0; i < 128; i++) s += p[(size_t)i * 256];
    out[(size_t)b * 256 + f] = s;
}

// ---------------------------------------------------------------------------
extern "C" void kernel_launch(void* const* d_in, const int* in_sizes, int n_in,
                              void* d_out, int out_size)
{
    const float* x = (const float*)d_in[0];
    // d_in[1] = batch_mask (unused: uniform graph layout)
    const float* W[3]    = {(const float*)d_in[2], (const float*)d_in[6],  (const float*)d_in[10]};
    const float* asv[3]  = {(const float*)d_in[3], (const float*)d_in[7],  (const float*)d_in[11]};
    const float* adv[3]  = {(const float*)d_in[4], (const float*)d_in[8],  (const float*)d_in[12]};
    const float* bias[3] = {(const float*)d_in[5], (const float*)d_in[9],  (const float*)d_in[13]};

    float *pH, *pX, *pS, *pD;
    cudaGetSymbolAddress((void**)&pH, g_H);
    cudaGetSymbolAddress((void**)&pX, g_X);
    cudaGetSymbolAddress((void**)&pS, g_S);
    cudaGetSymbolAddress((void**)&pD, g_D);

    cudaFuncSetAttribute(attn_kernel,
                         cudaFuncAttributeMaxDynamicSharedMemorySize, ATTN_SMEM);

    for (int l = 0; l < 3; l++) {
        const int K = (l == 0) ? 128 : 256;
        const float* A = (l == 0) ? x : pX;
        gemm_kernel<<<dim3(512, 4), 256>>>(A, W[l], pH, K);
        scores_kernel<<<8192, 256>>>(pH, asv[l], adv[l], pS, pD);
        attn_kernel<<<dim3(512, 4), 256, ATTN_SMEM>>>(pH, pS, pD, bias[l], pX);
    }
    reduce_kernel<<<512, 256>>>(pX, (float*)d_out);
}

// round 3
// speedup vs baseline: 2.0948x; 2.0948x over previous
#include <cuda_runtime.h>
#include <cstdint>
#include <math.h>

#define B_GRAPHS 512
#define N_NODES  128
#define F_OUT    256
#define HEADS    4
#define HID      64
#define M_TOT    (B_GRAPHS * N_NODES)   // 65536

__device__ float g_H[(size_t)M_TOT * F_OUT];
__device__ float g_X[(size_t)M_TOT * F_OUT];
__device__ float g_S[(size_t)M_TOT * HEADS];
__device__ float g_D[(size_t)M_TOT * HEADS];
__device__ float g_Wt[256 * 256];              // W transposed [n][k], tf32-rounded

// ---------------------------------------------------------------------------
#define CP_ASYNC16(dst, src) \
    asm volatile("cp.async.cg.shared.global [%0], [%1], 16;" \
        :: "r"((uint32_t)(dst)), "l"(src) : "memory")
#define CP_COMMIT() asm volatile("cp.async.commit_group;" ::: "memory")
#define CP_WAIT1()  asm volatile("cp.async.wait_group 1;" ::: "memory")
#define CP_WAIT0()  asm volatile("cp.async.wait_group 0;" ::: "memory")

__device__ __forceinline__ uint32_t smem_to_u32(const void* p) {
    uint32_t a;
    asm("{ .reg .u64 t; cvta.to.shared.u64 t, %1; cvt.u32.u64 %0, t; }"
        : "=r"(a) : "l"(p));
    return a;
}

__device__ __forceinline__ uint32_t tf32r(float f) {
    uint32_t u;
    asm("cvt.rna.tf32.f32 %0, %1;" : "=r"(u) : "f"(f));
    return u;
}

__device__ __forceinline__ void mma_tf32(
    float& d0, float& d1, float& d2, float& d3,
    uint32_t a0, uint32_t a1, uint32_t a2, uint32_t a3,
    uint32_t b0, uint32_t b1)
{
    asm volatile(
        "mma.sync.aligned.m16n8k8.row.col.f32.tf32.tf32.f32 "
        "{%0,%1,%2,%3}, {%4,%5,%6,%7}, {%8,%9}, {%0,%1,%2,%3};"
        : "+f"(d0), "+f"(d1), "+f"(d2), "+f"(d3)
        : "r"(a0), "r"(a1), "r"(a2), "r"(a3), "r"(b0), "r"(b1));
}

// ---------------------------------------------------------------------------
// W transpose + tf32 round: Wt[n][k] = rna_tf32(W[k][n])
// ---------------------------------------------------------------------------
__global__ __launch_bounds__(256) void transpose_kernel(
    const float* __restrict__ W, float* __restrict__ Wt, int K)
{
    int t = blockIdx.x * 256 + threadIdx.x;    // t = k*256 + n
    int k = t >> 8, n = t & 255;
    ((uint32_t*)Wt)[(size_t)n * K + k] = tf32r(W[t]);
}

// ===========================================================================
// GEMM: H[M,256] = A[M,K] @ Wt^T  via mma.sync tf32, fused att scores.
// 512 threads, 16 warps (wm = warp&3 -> 32 rows, wn = warp>>2 -> head/64 cols)
// Smem rows padded to 36 floats (144B): fragment LDS conflict-free.
// ===========================================================================
#define AS_STG 18432                       // 128 * 144
#define BS_STG 36864                       // 256 * 144
#define OFF_AS 2048
#define OFF_BS (OFF_AS + 2 * AS_STG)
#define GEMM_SMEM (OFF_BS + 2 * BS_STG)    // 112640

__global__ __launch_bounds__(512) void gemm_tc_kernel(
    const float* __restrict__ A, const float* __restrict__ Wt,
    const float* __restrict__ att_src, const float* __restrict__ att_dst,
    float* __restrict__ H, float* __restrict__ S, float* __restrict__ D,
    int K)
{
    extern __shared__ char sm[];
    float* atts = (float*)sm;              // 256 floats
    float* attd = (float*)(sm + 1024);
    uint32_t sb = smem_to_u32(sm);

    const int tid = threadIdx.x;
    const int warp = tid >> 5, lane = tid & 31;
    const int gid = lane >> 2, tig = lane & 3;
    const int wm = warp & 3, wn = warp >> 2;
    const int m0 = blockIdx.x * 128;

    if (tid < 256) { atts[tid] = att_src[tid]; attd[tid] = att_dst[tid]; }

    float acc[2][8][4];
#pragma unroll
    for (int mt = 0; mt < 2; mt++)
#pragma unroll
        for (int nt = 0; nt < 8; nt++)
#pragma unroll
            for (int c = 0; c < 4; c++) acc[mt][nt][c] = 0.f;

    const int NC = K >> 5;

    // chunk loader: A 128x32 (2 f4/thr), B 256x32 (4 f4/thr)
    auto load_chunk = [&](int k0, int stage) {
        uint32_t ab = sb + OFF_AS + stage * AS_STG;
        uint32_t bb = sb + OFF_BS + stage * BS_STG;
#pragma unroll
        for (int i = 0; i < 2; i++) {
            int g = tid + i * 512;
            int row = g >> 3, c = g & 7;
            CP_ASYNC16(ab + row * 144 + c * 16,
                       A + (size_t)(m0 + row) * K + k0 + c * 4);
        }
#pragma unroll
        for (int i = 0; i < 4; i++) {
            int g = tid + i * 512;
            int row = g >> 3, c = g & 7;
            CP_ASYNC16(bb + row * 144 + c * 16,
                       Wt + (size_t)row * K + k0 + c * 4);
        }
    };

    load_chunk(0, 0);
    CP_COMMIT();

    for (int c = 0; c < NC; c++) {
        if (c + 1 < NC) {
            load_chunk((c + 1) << 5, (c + 1) & 1);
            CP_COMMIT();
            CP_WAIT1();
        } else {
            CP_WAIT0();
        }
        __syncthreads();

        const float* As = (const float*)(sm + OFF_AS + (c & 1) * AS_STG);
        const uint32_t* Bs = (const uint32_t*)(sm + OFF_BS + (c & 1) * BS_STG);

#pragma unroll
        for (int kk = 0; kk < 4; kk++) {
            uint32_t a[2][4];
#pragma unroll
            for (int mt = 0; mt < 2; mt++) {
                int r = (wm * 32 + mt * 16 + gid) * 36 + kk * 8 + tig;
                a[mt][0] = tf32r(As[r]);
                a[mt][1] = tf32r(As[r + 8 * 36]);
                a[mt][2] = tf32r(As[r + 4]);
                a[mt][3] = tf32r(As[r + 8 * 36 + 4]);
            }
            uint32_t b[8][2];
#pragma unroll
            for (int nt = 0; nt < 8; nt++) {
                int r = (wn * 64 + nt * 8 + gid) * 36 + kk * 8 + tig;
                b[nt][0] = Bs[r];
                b[nt][1] = Bs[r + 4];
            }
#pragma unroll
            for (int mt = 0; mt < 2; mt++)
#pragma unroll
                for (int nt = 0; nt < 8; nt++)
                    mma_tf32(acc[mt][nt][0], acc[mt][nt][1],
                             acc[mt][nt][2], acc[mt][nt][3],
                             a[mt][0], a[mt][1], a[mt][2], a[mt][3],
                             b[nt][0], b[nt][1]);
        }
        __syncthreads();
    }

    // Epilogue: store H + fused per-head scores (warp wn == head wn)
#pragma unroll
    for (int mt = 0; mt < 2; mt++) {
#pragma unroll
        for (int h2 = 0; h2 < 2; h2++) {
            int rl = wm * 32 + mt * 16 + gid + 8 * h2;
            float* orow = H + (size_t)(m0 + rl) * 256 + wn * 64;
            float s = 0.f, d = 0.f;
#pragma unroll
            for (int nt = 0; nt < 8; nt++) {
                int col = wn * 64 + nt * 8 + tig * 2;
                float v0 = acc[mt][nt][h2 * 2], v1 = acc[mt][nt][h2 * 2 + 1];
                s = fmaf(v0, atts[col], s);  s = fmaf(v1, atts[col + 1], s);
                d = fmaf(v0, attd[col], d);  d = fmaf(v1, attd[col + 1], d);
                *(float2*)&orow[nt * 8 + tig * 2] = make_float2(v0, v1);
            }
            s += __shfl_xor_sync(0xffffffffu, s, 1);
            s += __shfl_xor_sync(0xffffffffu, s, 2);
            d += __shfl_xor_sync(0xffffffffu, d, 1);
            d += __shfl_xor_sync(0xffffffffu, d, 2);
            if (tig == 0) {
                S[(size_t)(m0 + rl) * 4 + wn] = s;
                D[(size_t)(m0 + rl) * 4 + wn] = d;
            }
        }
    }
}

// ===========================================================================
// Attention per (b,h): softmax P in smem (tf32-rounded), OUT = P@Hs via mma.
// 256 threads, 8 warps: wm = warp&3 (32 rows), wn = warp>>2 (32 cols).
// ===========================================================================
#define PSTR 132
#define ATTN_SMEM ((128 * PSTR + 64 * PSTR + 256) * 4)

__global__ __launch_bounds__(256) void attn_tc_kernel(
    const float* __restrict__ H, const float* __restrict__ S,
    const float* __restrict__ D, const float* __restrict__ bias,
    float* __restrict__ OUT)
{
    extern __shared__ float smf[];
    float* P  = smf;                    // [128][132]
    float* Ht = smf + 128 * PSTR;       // [64][132]  transposed H tile
    float* sv = Ht + 64 * PSTR;         // [128]
    float* dv = sv + 128;               // [128]

    const int b = blockIdx.x, h = blockIdx.y;
    const int tid = threadIdx.x, lane = tid & 31, warp = tid >> 5;
    const int gid = lane >> 2, tig = lane & 3;

    // Stage H tile transposed + tf32-rounded: Ht[c][j] = rna(H[b, j, 64h + c])
    const float* Hb = H + (size_t)b * 128 * 256 + h * 64;
    for (int idx = tid; idx < 128 * 16; idx += 256) {
        int j = idx >> 4, c4 = (idx & 15) << 2;
        float4 v = *(const float4*)&Hb[(size_t)j * 256 + c4];
        ((uint32_t*)Ht)[(c4 + 0) * PSTR + j] = tf32r(v.x);
        ((uint32_t*)Ht)[(c4 + 1) * PSTR + j] = tf32r(v.y);
        ((uint32_t*)Ht)[(c4 + 2) * PSTR + j] = tf32r(v.z);
        ((uint32_t*)Ht)[(c4 + 3) * PSTR + j] = tf32r(v.w);
    }
    if (tid < 128) sv[tid] = S[((size_t)b * 128 + tid) * 4 + h];
    else { int t = tid - 128; dv[t] = D[((size_t)b * 128 + t) * 4 + h]; }
    __syncthreads();

    // Phase 1: softmax rows (16 per warp), tf32-rounded store
#pragma unroll 1
    for (int r = 0; r < 16; r++) {
        int i = warp * 16 + r;
        float di = dv[i];
        float v[4];
        float m = -1e30f;
#pragma unroll
        for (int q = 0; q < 4; q++) {
            float a = sv[lane + q * 32] + di;
            v[q] = (a >= 0.f) ? a : 0.2f * a;
            m = fmaxf(m, v[q]);
        }
#pragma unroll
        for (int off = 16; off; off >>= 1)
            m = fmaxf(m, __shfl_xor_sync(0xffffffffu, m, off));
        float sum = 0.f;
#pragma unroll
        for (int q = 0; q < 4; q++) { v[q] = __expf(v[q] - m); sum += v[q]; }
#pragma unroll
        for (int off = 16; off; off >>= 1)
            sum += __shfl_xor_sync(0xffffffffu, sum, off);
        float inv = 1.0f / sum;
#pragma unroll
        for (int q = 0; q < 4; q++)
            ((uint32_t*)P)[i * PSTR + lane + q * 32] = tf32r(v[q] * inv);
    }
    __syncthreads();

    // Phase 2: OUT(128x64) = P(128x128) @ Ht^T via m16n8k8
    const int wm = warp & 3, wn = warp >> 2;   // wn in {0,1}
    float acc[2][4][4];
#pragma unroll
    for (int mt = 0; mt < 2; mt++)
#pragma unroll
        for (int nt = 0; nt < 4; nt++)
#pragma unroll
            for (int c = 0; c < 4; c++) acc[mt][nt][c] = 0.f;

    const uint32_t* Pu = (const uint32_t*)P;
    const uint32_t* Hu = (const uint32_t*)Ht;
#pragma unroll
    for (int kk = 0; kk < 16; kk++) {
        uint32_t a[2][4];
#pragma unroll
        for (int mt = 0; mt < 2; mt++) {
            int r = (wm * 32 + mt * 16 + gid) * PSTR + kk * 8 + tig;
            a[mt][0] = Pu[r];
            a[mt][1] = Pu[r + 8 * PSTR];
            a[mt][2] = Pu[r + 4];
            a[mt][3] = Pu[r + 8 * PSTR + 4];
        }
        uint32_t bb[4][2];
#pragma unroll
        for (int nt = 0; nt < 4; nt++) {
            int r = (wn * 32 + nt * 8 + gid) * PSTR + kk * 8 + tig;
            bb[nt][0] = Hu[r];
            bb[nt][1] = Hu[r + 4];
        }
#pragma unroll
        for (int mt = 0; mt < 2; mt++)
#pragma unroll
            for (int nt = 0; nt < 4; nt++)
                mma_tf32(acc[mt][nt][0], acc[mt][nt][1],
                         acc[mt][nt][2], acc[mt][nt][3],
                         a[mt][0], a[mt][1], a[mt][2], a[mt][3],
                         bb[nt][0], bb[nt][1]);
    }

    // Epilogue: bias + store
#pragma unroll
    for (int mt = 0; mt < 2; mt++)
#pragma unroll
        for (int h2 = 0; h2 < 2; h2++) {
            int row = wm * 32 + mt * 16 + gid + 8 * h2;
            float* o = OUT + ((size_t)b * 128 + row) * 256 + h * 64;
#pragma unroll
            for (int nt = 0; nt < 4; nt++) {
                int col = wn * 32 + nt * 8 + tig * 2;
                float2 r = make_float2(acc[mt][nt][h2 * 2] + bias[h * 64 + col],
                                       acc[mt][nt][h2 * 2 + 1] + bias[h * 64 + col + 1]);
                *(float2*)&o[col] = r;
            }
        }
}

// ---------------------------------------------------------------------------
__global__ __launch_bounds__(256) void reduce_kernel(
    const float* __restrict__ X, float* __restrict__ out)
{
    const int b = blockIdx.x, f = threadIdx.x;
    const float* p = X + (size_t)b * 128 * 256 + f;
    float s = 0.f;
#pragma unroll 8
    for (int i = 0; i < 128; i++) s += p[(size_t)i * 256];
    out[(size_t)b * 256 + f] = s;
}

// ---------------------------------------------------------------------------
extern "C" void kernel_launch(void* const* d_in, const int* in_sizes, int n_in,
                              void* d_out, int out_size)
{
    const float* x = (const float*)d_in[0];
    const float* W[3]    = {(const float*)d_in[2], (const float*)d_in[6],  (const float*)d_in[10]};
    const float* asv[3]  = {(const float*)d_in[3], (const float*)d_in[7],  (const float*)d_in[11]};
    const float* adv[3]  = {(const float*)d_in[4], (const float*)d_in[8],  (const float*)d_in[12]};
    const float* bias[3] = {(const float*)d_in[5], (const float*)d_in[9],  (const float*)d_in[13]};

    float *pH, *pX, *pS, *pD, *pWt;
    cudaGetSymbolAddress((void**)&pH, g_H);
    cudaGetSymbolAddress((void**)&pX, g_X);
    cudaGetSymbolAddress((void**)&pS, g_S);
    cudaGetSymbolAddress((void**)&pD, g_D);
    cudaGetSymbolAddress((void**)&pWt, g_Wt);

    cudaFuncSetAttribute(gemm_tc_kernel,
                         cudaFuncAttributeMaxDynamicSharedMemorySize, GEMM_SMEM);
    cudaFuncSetAttribute(attn_tc_kernel,
                         cudaFuncAttributeMaxDynamicSharedMemorySize, ATTN_SMEM);

    for (int l = 0; l < 3; l++) {
        const int K = (l == 0) ? 128 : 256;
        const float* A = (l == 0) ? x : pX;
        transpose_kernel<<<K, 256>>>(W[l], pWt, K);
        gemm_tc_kernel<<<512, 512, GEMM_SMEM>>>(A, pWt, asv[l], adv[l],
                                                pH, pS, pD, K);
        attn_tc_kernel<<<dim3(512, 4), 256, ATTN_SMEM>>>(pH, pS, pD, bias[l], pX);
    }
    reduce_kernel<<<512, 256>>>(pX, (float*)d_out);
}

// round 4
// speedup vs baseline: 2.4788x; 1.1833x over previous
#include <cuda_runtime.h>
#include <cstdint>
#include <math.h>

#define B_GRAPHS 512
#define N_NODES  128
#define F_OUT    256
#define HEADS    4
#define HID      64
#define M_TOT    (B_GRAPHS * N_NODES)   // 65536

__device__ float g_X[(size_t)M_TOT * F_OUT];   // inter-layer activations
__device__ float g_Wt[3][256 * 256];           // per-layer transposed weights [n][k]

// ---------------------------------------------------------------------------
#define CP_ASYNC16(dst, src) \
    asm volatile("cp.async.cg.shared.global [%0], [%1], 16;" \
        :: "r"((uint32_t)(dst)), "l"(src) : "memory")
#define CP_COMMIT() asm volatile("cp.async.commit_group;" ::: "memory")
#define CP_WAIT1()  asm volatile("cp.async.wait_group 1;" ::: "memory")
#define CP_WAIT0()  asm volatile("cp.async.wait_group 0;" ::: "memory")

__device__ __forceinline__ uint32_t smem_to_u32(const void* p) {
    uint32_t a;
    asm("{ .reg .u64 t; cvta.to.shared.u64 t, %1; cvt.u32.u64 %0, t; }"
        : "=r"(a) : "l"(p));
    return a;
}

__device__ __forceinline__ uint32_t tf32r(float f) {
    uint32_t u;
    asm("cvt.rna.tf32.f32 %0, %1;" : "=r"(u) : "f"(f));
    return u;
}

__device__ __forceinline__ void mma_tf32(
    float& d0, float& d1, float& d2, float& d3,
    uint32_t a0, uint32_t a1, uint32_t a2, uint32_t a3,
    uint32_t b0, uint32_t b1)
{
    asm volatile(
        "mma.sync.aligned.m16n8k8.row.col.f32.tf32.tf32.f32 "
        "{%0,%1,%2,%3}, {%4,%5,%6,%7}, {%8,%9}, {%0,%1,%2,%3};"
        : "+f"(d0), "+f"(d1), "+f"(d2), "+f"(d3)
        : "r"(a0), "r"(a1), "r"(a2), "r"(a3), "r"(b0), "r"(b1));
}

// ---------------------------------------------------------------------------
// Transpose all three weight matrices in one launch (tf32-rounded).
// W0: 128x256 -> Wt[0] [256][128]; W1,W2: 256x256 -> Wt[1,2] [256][256]
// ---------------------------------------------------------------------------
__global__ __launch_bounds__(256) void transpose_all_kernel(
    const float* __restrict__ W0, const float* __restrict__ W1,
    const float* __restrict__ W2, float* __restrict__ Wt)
{
    int t = blockIdx.x * 256 + threadIdx.x;
    uint32_t* o = (uint32_t*)Wt;
    if (t < 128 * 256) {
        int k = t >> 8, n = t & 255;
        o[(size_t)n * 128 + k] = tf32r(W0[t]);
    } else if (t < 128 * 256 + 256 * 256) {
        int t2 = t - 128 * 256;
        int k = t2 >> 8, n = t2 & 255;
        o[65536 + (size_t)n * 256 + k] = tf32r(W1[t2]);
    } else {
        int t3 = t - 128 * 256 - 256 * 256;
        int k = t3 >> 8, n = t3 & 255;
        o[131072 + (size_t)n * 256 + k] = tf32r(W2[t3]);
    }
}

// ===========================================================================
// Fused layer kernel: one CTA per graph (512 threads, 16 warps).
//  1. H[128][256] = A[128][K] @ Wt^T     (tf32 mma, double-buffered cp.async)
//  2. epilogue: Ht (transposed, tf32) + scores S/D into smem
//  3. per head: softmax P (tf32, smem) ; OUT = P @ Ht^T (tf32 mma)
//  4. OUT -> X (+bias), or for the last layer: node-sum -> out (+128*bias)
// ===========================================================================
#define PSTR 132
#define OFF_ATTS   0
#define OFF_ATTD   1024
#define OFF_SV     2048                     // [4][128] f32
#define OFF_DV     4096
#define OFF_RED    6144                     // [4][256] f32
#define OFF_BIAS   10240
#define OFF_STAGE  11264                    // A: 2x18432, B: 2x36864
#define AS_STG     18432                    // 128 rows * 144B
#define BS_STG     36864                    // 256 rows * 144B
#define OFF_BSTG   (OFF_STAGE + 2 * AS_STG)
#define OFF_HT     11264                    // union over staging: [256][132] f32
#define OFF_P      (OFF_HT + 256 * PSTR * 4)      // [128][132] f32
#define LAYER_SMEM (OFF_P + 128 * PSTR * 4)       // 214016 bytes

__global__ __launch_bounds__(512) void layer_kernel(
    const float* __restrict__ A, const float* __restrict__ Wt,
    const float* __restrict__ att_src, const float* __restrict__ att_dst,
    const float* __restrict__ bias_g,
    float* __restrict__ X, float* __restrict__ out_final,
    int K, int last)
{
    extern __shared__ char sm[];
    uint32_t sb = smem_to_u32(sm);
    float* atts  = (float*)(sm + OFF_ATTS);
    float* attd  = (float*)(sm + OFF_ATTD);
    float* sv    = (float*)(sm + OFF_SV);
    float* dv    = (float*)(sm + OFF_DV);
    float* red   = (float*)(sm + OFF_RED);
    float* biass = (float*)(sm + OFF_BIAS);
    uint32_t* Htu = (uint32_t*)(sm + OFF_HT);
    uint32_t* Pu  = (uint32_t*)(sm + OFF_P);

    const int tid = threadIdx.x;
    const int warp = tid >> 5, lane = tid & 31;
    const int gid = lane >> 2, tig = lane & 3;
    const int wm = warp & 3, wn = warp >> 2;        // GEMM: 4x4 warp grid
    const int b = blockIdx.x;
    const int m0 = b * 128;

    if (tid < 256) {
        atts[tid]  = att_src[tid];
        attd[tid]  = att_dst[tid];
        biass[tid] = bias_g[tid];
    }

    // ---------------- Phase 1: GEMM ----------------
    float acc[2][8][4];
#pragma unroll
    for (int mt = 0; mt < 2; mt++)
#pragma unroll
        for (int nt = 0; nt < 8; nt++)
#pragma unroll
            for (int c = 0; c < 4; c++) acc[mt][nt][c] = 0.f;

    const int NC = K >> 5;
    auto load_chunk = [&](int k0, int stage) {
        uint32_t ab = sb + OFF_STAGE + stage * AS_STG;
        uint32_t bb = sb + OFF_BSTG + stage * BS_STG;
#pragma unroll
        for (int i = 0; i < 2; i++) {
            int g = tid + i * 512;
            int row = g >> 3, c = g & 7;
            CP_ASYNC16(ab + row * 144 + c * 16,
                       A + (size_t)(m0 + row) * K + k0 + c * 4);
        }
#pragma unroll
        for (int i = 0; i < 4; i++) {
            int g = tid + i * 512;
            int row = g >> 3, c = g & 7;
            CP_ASYNC16(bb + row * 144 + c * 16,
                       Wt + (size_t)row * K + k0 + c * 4);
        }
    };

    load_chunk(0, 0);
    CP_COMMIT();

    for (int c = 0; c < NC; c++) {
        if (c + 1 < NC) {
            load_chunk((c + 1) << 5, (c + 1) & 1);
            CP_COMMIT();
            CP_WAIT1();
        } else {
            CP_WAIT0();
        }
        __syncthreads();

        const float* As = (const float*)(sm + OFF_STAGE + (c & 1) * AS_STG);
        const uint32_t* Bs = (const uint32_t*)(sm + OFF_BSTG + (c & 1) * BS_STG);
#pragma unroll
        for (int kk = 0; kk < 4; kk++) {
            uint32_t a[2][4];
#pragma unroll
            for (int mt = 0; mt < 2; mt++) {
                int r = (wm * 32 + mt * 16 + gid) * 36 + kk * 8 + tig;
                a[mt][0] = tf32r(As[r]);
                a[mt][1] = tf32r(As[r + 8 * 36]);
                a[mt][2] = tf32r(As[r + 4]);
                a[mt][3] = tf32r(As[r + 8 * 36 + 4]);
            }
            uint32_t bf[8][2];
#pragma unroll
            for (int nt = 0; nt < 8; nt++) {
                int r = (wn * 64 + nt * 8 + gid) * 36 + kk * 8 + tig;
                bf[nt][0] = Bs[r];
                bf[nt][1] = Bs[r + 4];
            }
#pragma unroll
            for (int mt = 0; mt < 2; mt++)
#pragma unroll
                for (int nt = 0; nt < 8; nt++)
                    mma_tf32(acc[mt][nt][0], acc[mt][nt][1],
                             acc[mt][nt][2], acc[mt][nt][3],
                             a[mt][0], a[mt][1], a[mt][2], a[mt][3],
                             bf[nt][0], bf[nt][1]);
        }
        __syncthreads();
    }

    // ---------------- Phase 2: epilogue -> Ht (transposed tf32) + scores ----
#pragma unroll
    for (int mt = 0; mt < 2; mt++) {
#pragma unroll
        for (int h2 = 0; h2 < 2; h2++) {
            int rl = wm * 32 + mt * 16 + gid + 8 * h2;
            float s = 0.f, d = 0.f;
#pragma unroll
            for (int nt = 0; nt < 8; nt++) {
                int col = wn * 64 + nt * 8 + tig * 2;
                float v0 = acc[mt][nt][h2 * 2], v1 = acc[mt][nt][h2 * 2 + 1];
                s = fmaf(v0, atts[col], s);  s = fmaf(v1, atts[col + 1], s);
                d = fmaf(v0, attd[col], d);  d = fmaf(v1, attd[col + 1], d);
                Htu[(col) * PSTR + rl]     = tf32r(v0);
                Htu[(col + 1) * PSTR + rl] = tf32r(v1);
            }
            s += __shfl_xor_sync(0xffffffffu, s, 1);
            s += __shfl_xor_sync(0xffffffffu, s, 2);
            d += __shfl_xor_sync(0xffffffffu, d, 1);
            d += __shfl_xor_sync(0xffffffffu, d, 2);
            if (tig == 0) {
                sv[wn * 128 + rl] = s;
                dv[wn * 128 + rl] = d;
            }
        }
    }
    __syncthreads();

    // ---------------- Phase 3: per-head softmax + P@Ht ----------------
    const int wn2 = warp >> 2;     // 0..3 : 16-col slice of OUT
#pragma unroll 1
    for (int h = 0; h < 4; h++) {
        // softmax: 8 rows per warp
#pragma unroll 1
        for (int r = 0; r < 8; r++) {
            int i = warp * 8 + r;
            float di = dv[h * 128 + i];
            float v[4];
            float m = -1e30f;
#pragma unroll
            for (int q = 0; q < 4; q++) {
                float a = sv[h * 128 + lane + q * 32] + di;
                v[q] = (a >= 0.f) ? a : 0.2f * a;
                m = fmaxf(m, v[q]);
            }
#pragma unroll
            for (int off = 16; off; off >>= 1)
                m = fmaxf(m, __shfl_xor_sync(0xffffffffu, m, off));
            float sum = 0.f;
#pragma unroll
            for (int q = 0; q < 4; q++) { v[q] = __expf(v[q] - m); sum += v[q]; }
#pragma unroll
            for (int off = 16; off; off >>= 1)
                sum += __shfl_xor_sync(0xffffffffu, sum, off);
            float inv = 1.0f / sum;
#pragma unroll
            for (int q = 0; q < 4; q++)
                Pu[i * PSTR + lane + q * 32] = tf32r(v[q] * inv);
        }
        __syncthreads();

        // OUT(128x64) = P(128x128) @ Ht(h)^T : warp (wm, wn2) -> 32x16 tile
        float a2[2][2][4];
#pragma unroll
        for (int mt = 0; mt < 2; mt++)
#pragma unroll
            for (int nt = 0; nt < 2; nt++)
#pragma unroll
                for (int c = 0; c < 4; c++) a2[mt][nt][c] = 0.f;

        const uint32_t* Hh = Htu + (size_t)h * 64 * PSTR;
#pragma unroll
        for (int kk = 0; kk < 16; kk++) {
            uint32_t a[2][4];
#pragma unroll
            for (int mt = 0; mt < 2; mt++) {
                int r = (wm * 32 + mt * 16 + gid) * PSTR + kk * 8 + tig;
                a[mt][0] = Pu[r];
                a[mt][1] = Pu[r + 8 * PSTR];
                a[mt][2] = Pu[r + 4];
                a[mt][3] = Pu[r + 8 * PSTR + 4];
            }
            uint32_t bf[2][2];
#pragma unroll
            for (int nt = 0; nt < 2; nt++) {
                int r = (wn2 * 16 + nt * 8 + gid) * PSTR + kk * 8 + tig;
                bf[nt][0] = Hh[r];
                bf[nt][1] = Hh[r + 4];
            }
#pragma unroll
            for (int mt = 0; mt < 2; mt++)
#pragma unroll
                for (int nt = 0; nt < 2; nt++)
                    mma_tf32(a2[mt][nt][0], a2[mt][nt][1],
                             a2[mt][nt][2], a2[mt][nt][3],
                             a[mt][0], a[mt][1], a[mt][2], a[mt][3],
                             bf[nt][0], bf[nt][1]);
        }

        if (!last) {
#pragma unroll
            for (int mt = 0; mt < 2; mt++)
#pragma unroll
                for (int h2 = 0; h2 < 2; h2++) {
                    int row = wm * 32 + mt * 16 + gid + 8 * h2;
                    float* o = X + ((size_t)m0 + row) * 256 + h * 64;
#pragma unroll
                    for (int nt = 0; nt < 2; nt++) {
                        int col = wn2 * 16 + nt * 8 + tig * 2;
                        float2 rv = make_float2(
                            a2[mt][nt][h2 * 2]     + biass[h * 64 + col],
                            a2[mt][nt][h2 * 2 + 1] + biass[h * 64 + col + 1]);
                        *(float2*)&o[col] = rv;
                    }
                }
        } else {
            // node-sum: reduce 32 rows of this warp's tile, no X write
#pragma unroll
            for (int nt = 0; nt < 2; nt++) {
                float p0 = a2[0][nt][0] + a2[0][nt][2] + a2[1][nt][0] + a2[1][nt][2];
                float p1 = a2[0][nt][1] + a2[0][nt][3] + a2[1][nt][1] + a2[1][nt][3];
#pragma unroll
                for (int off = 4; off < 32; off <<= 1) {
                    p0 += __shfl_xor_sync(0xffffffffu, p0, off);
                    p1 += __shfl_xor_sync(0xffffffffu, p1, off);
                }
                if (gid == 0) {
                    int col = h * 64 + wn2 * 16 + nt * 8 + tig * 2;
                    red[wm * 256 + col]     = p0;
                    red[wm * 256 + col + 1] = p1;
                }
            }
        }
        __syncthreads();
    }

    if (last && tid < 256) {
        float s = red[tid] + red[256 + tid] + red[512 + tid] + red[768 + tid];
        out_final[(size_t)b * 256 + tid] = s + 128.f * biass[tid];
    }
}

// ---------------------------------------------------------------------------
extern "C" void kernel_launch(void* const* d_in, const int* in_sizes, int n_in,
                              void* d_out, int out_size)
{
    const float* x = (const float*)d_in[0];
    const float* W[3]    = {(const float*)d_in[2], (const float*)d_in[6],  (const float*)d_in[10]};
    const float* asv[3]  = {(const float*)d_in[3], (const float*)d_in[7],  (const float*)d_in[11]};
    const float* adv[3]  = {(const float*)d_in[4], (const float*)d_in[8],  (const float*)d_in[12]};
    const float* bias[3] = {(const float*)d_in[5], (const float*)d_in[9],  (const float*)d_in[13]};

    float *pX, *pWt;
    cudaGetSymbolAddress((void**)&pX, g_X);
    cudaGetSymbolAddress((void**)&pWt, g_Wt);

    cudaFuncSetAttribute(layer_kernel,
                         cudaFuncAttributeMaxDynamicSharedMemorySize, LAYER_SMEM);

    transpose_all_kernel<<<640, 256>>>(W[0], W[1], W[2], pWt);

    for (int l = 0; l < 3; l++) {
        const int K = (l == 0) ? 128 : 256;
        const float* A = (l == 0) ? x : pX;
        const float* Wtl = pWt + (size_t)l * 65536;
        layer_kernel<<<512, 512, LAYER_SMEM>>>(
            A, Wtl, asv[l], adv[l], bias[l],
            pX, (float*)d_out, K, l == 2);
    }
}

// round 6
// speedup vs baseline: 2.5748x; 1.0387x over previous
#include <cuda_runtime.h>
#include <cstdint>
#include <math.h>

#define B_GRAPHS 512
#define N_NODES  128
#define F_OUT    256
#define HEADS    4
#define HID      64
#define M_TOT    (B_GRAPHS * N_NODES)   // 65536

__device__ float g_X[(size_t)M_TOT * F_OUT];   // layer-0 output
__device__ float g_Y[(size_t)M_TOT * F_OUT];   // layer-1 output
__device__ float g_Wt[3][256 * 256];           // per-layer transposed weights [n][k]

// ---------------------------------------------------------------------------
#define CP_ASYNC16(dst, src) \
    asm volatile("cp.async.cg.shared.global [%0], [%1], 16;" \
        :: "r"((uint32_t)(dst)), "l"(src) : "memory")
#define CP_COMMIT() asm volatile("cp.async.commit_group;" ::: "memory")
#define CP_WAIT1()  asm volatile("cp.async.wait_group 1;" ::: "memory")
#define CP_WAIT0()  asm volatile("cp.async.wait_group 0;" ::: "memory")

__device__ __forceinline__ uint32_t smem_to_u32(const void* p) {
    uint32_t a;
    asm("{ .reg .u64 t; cvta.to.shared.u64 t, %1; cvt.u32.u64 %0, t; }"
        : "=r"(a) : "l"(p));
    return a;
}

__device__ __forceinline__ uint32_t tf32r(float f) {
    uint32_t u;
    asm("cvt.rna.tf32.f32 %0, %1;" : "=r"(u) : "f"(f));
    return u;
}

__device__ __forceinline__ void mma_tf32(
    float& d0, float& d1, float& d2, float& d3,
    uint32_t a0, uint32_t a1, uint32_t a2, uint32_t a3,
    uint32_t b0, uint32_t b1)
{
    asm volatile(
        "mma.sync.aligned.m16n8k8.row.col.f32.tf32.tf32.f32 "
        "{%0,%1,%2,%3}, {%4,%5,%6,%7}, {%8,%9}, {%0,%1,%2,%3};"
        : "+f"(d0), "+f"(d1), "+f"(d2), "+f"(d3)
        : "r"(a0), "r"(a1), "r"(a2), "r"(a3), "r"(b0), "r"(b1));
}

// ---------------------------------------------------------------------------
// Transpose all three weight matrices in one launch (tf32-rounded).
// ---------------------------------------------------------------------------
__global__ __launch_bounds__(256) void transpose_all_kernel(
    const float* __restrict__ W0, const float* __restrict__ W1,
    const float* __restrict__ W2, float* __restrict__ Wt)
{
    int t = blockIdx.x * 256 + threadIdx.x;
    uint32_t* o = (uint32_t*)Wt;
    if (t < 128 * 256) {
        int k = t >> 8, n = t & 255;
        o[(size_t)n * 128 + k] = tf32r(W0[t]);
    } else if (t < 128 * 256 + 256 * 256) {
        int t2 = t - 128 * 256;
        int k = t2 >> 8, n = t2 & 255;
        o[65536 + (size_t)n * 256 + k] = tf32r(W1[t2]);
    } else {
        int t3 = t - 128 * 256 - 256 * 256;
        int k = t3 >> 8, n = t3 & 255;
        o[131072 + (size_t)n * 256 + k] = tf32r(W2[t3]);
    }
}

// ===========================================================================
// Fused layer kernel, 2 CTAs/SM. One CTA per graph (512 threads, 16 warps).
// IMPORTANT: A (input) and X (output) must be DISTINCT buffers — the second
// N-half re-reads A from global after the first half wrote X.
// ===========================================================================
#define PSTR 132
#define OFF_SVP  3072                  // [4][128] f32 partial src scores
#define OFF_DVP  5120                  // [4][128] f32 partial dst scores
#define OFF_Q    7168                  // [128] f32
#define OFF_U    7680                  // union region
#define AS_STG   18432                 // 128 rows * 144B
#define OFF_HT2  0                     // (in U) Ht [2*64][132] = 67584
#define OFF_PB   67584                 // (in U) P  [64][132]   = 33792
#define U_SIZE   101376
#define LAYER_SMEM (OFF_U + U_SIZE)    // 109056 bytes -> 2 CTAs/SM

__global__ __launch_bounds__(512, 2) void layer_kernel(
    const float* __restrict__ A, const float* __restrict__ Wt,
    const float* __restrict__ att_src, const float* __restrict__ att_dst,
    const float* __restrict__ bias_g,
    float* __restrict__ X, float* __restrict__ out_final,
    int K, int last)
{
    extern __shared__ char sm[];
    uint32_t sb = smem_to_u32(sm);
    float* atts  = (float*)(sm);
    float* attd  = (float*)(sm + 1024);
    float* biass = (float*)(sm + 2048);
    float* svp   = (float*)(sm + OFF_SVP);
    float* dvp   = (float*)(sm + OFF_DVP);
    float* qbuf  = (float*)(sm + OFF_Q);
    uint32_t* Htu = (uint32_t*)(sm + OFF_U + OFF_HT2);
    uint32_t* Pu  = (uint32_t*)(sm + OFF_U + OFF_PB);

    const int tid = threadIdx.x;
    const int warp = tid >> 5, lane = tid & 31;
    const int gid = lane >> 2, tig = lane & 3;
    const int wm = warp & 3, wn = warp >> 2;
    const int b = blockIdx.x, m0 = b * 128;

    if (tid < 256) {
        atts[tid]  = att_src[tid];
        attd[tid]  = att_dst[tid];
        biass[tid] = bias_g[tid];
    }

    const int NC = K >> 5;

#pragma unroll 1
    for (int nh = 0; nh < 2; nh++) {
        // ---------------- GEMM half: 128 x 128 ----------------
        float acc[2][4][4];
#pragma unroll
        for (int mt = 0; mt < 2; mt++)
#pragma unroll
            for (int nt = 0; nt < 4; nt++)
#pragma unroll
                for (int c = 0; c < 4; c++) acc[mt][nt][c] = 0.f;

        auto load_chunk = [&](int k0, int stage) {
            uint32_t ab = sb + OFF_U + stage * AS_STG;
            uint32_t bb = sb + OFF_U + 2 * AS_STG + stage * AS_STG;
#pragma unroll
            for (int i = 0; i < 2; i++) {
                int g = tid + i * 512;
                int row = g >> 3, c = g & 7;
                CP_ASYNC16(ab + row * 144 + c * 16,
                           A + (size_t)(m0 + row) * K + k0 + c * 4);
            }
#pragma unroll
            for (int i = 0; i < 2; i++) {
                int g = tid + i * 512;
                int row = g >> 3, c = g & 7;
                CP_ASYNC16(bb + row * 144 + c * 16,
                           Wt + (size_t)(nh * 128 + row) * K + k0 + c * 4);
            }
        };

        load_chunk(0, 0);
        CP_COMMIT();

        for (int c = 0; c < NC; c++) {
            if (c + 1 < NC) {
                load_chunk((c + 1) << 5, (c + 1) & 1);
                CP_COMMIT();
                CP_WAIT1();
            } else {
                CP_WAIT0();
            }
            __syncthreads();

            const float* As = (const float*)(sm + OFF_U + (c & 1) * AS_STG);
            const uint32_t* Bs =
                (const uint32_t*)(sm + OFF_U + 2 * AS_STG + (c & 1) * AS_STG);
#pragma unroll
            for (int kk = 0; kk < 4; kk++) {
                uint32_t a[2][4];
#pragma unroll
                for (int mt = 0; mt < 2; mt++) {
                    int r = (wm * 32 + mt * 16 + gid) * 36 + kk * 8 + tig;
                    a[mt][0] = tf32r(As[r]);
                    a[mt][1] = tf32r(As[r + 8 * 36]);
                    a[mt][2] = tf32r(As[r + 4]);
                    a[mt][3] = tf32r(As[r + 8 * 36 + 4]);
                }
                uint32_t bf[4][2];
#pragma unroll
                for (int nt = 0; nt < 4; nt++) {
                    int r = (wn * 32 + nt * 8 + gid) * 36 + kk * 8 + tig;
                    bf[nt][0] = Bs[r];
                    bf[nt][1] = Bs[r + 4];
                }
#pragma unroll
                for (int mt = 0; mt < 2; mt++)
#pragma unroll
                    for (int nt = 0; nt < 4; nt++)
                        mma_tf32(acc[mt][nt][0], acc[mt][nt][1],
                                 acc[mt][nt][2], acc[mt][nt][3],
                                 a[mt][0], a[mt][1], a[mt][2], a[mt][3],
                                 bf[nt][0], bf[nt][1]);
            }
            __syncthreads();
        }

        // ---------------- epilogue: Ht + score partials ----------------
        const int hl_w = wn >> 1;          // warp's local head (0/1)
#pragma unroll
        for (int mt = 0; mt < 2; mt++) {
#pragma unroll
            for (int h2 = 0; h2 < 2; h2++) {
                int rl = wm * 32 + mt * 16 + gid + 8 * h2;
                float s = 0.f, d = 0.f;
#pragma unroll
                for (int nt = 0; nt < 4; nt++) {
                    int cl = (wn & 1) * 32 + nt * 8 + tig * 2;      // col in head
                    int gc = nh * 128 + wn * 32 + nt * 8 + tig * 2; // global col
                    float v0 = acc[mt][nt][h2 * 2], v1 = acc[mt][nt][h2 * 2 + 1];
                    s = fmaf(v0, atts[gc], s);  s = fmaf(v1, atts[gc + 1], s);
                    d = fmaf(v0, attd[gc], d);  d = fmaf(v1, attd[gc + 1], d);
                    Htu[(hl_w * 64 + cl) * PSTR + rl]       = tf32r(v0);
                    Htu[(hl_w * 64 + cl + 1) * PSTR + rl]   = tf32r(v1);
                }
                s += __shfl_xor_sync(0xffffffffu, s, 1);
                s += __shfl_xor_sync(0xffffffffu, s, 2);
                d += __shfl_xor_sync(0xffffffffu, d, 1);
                d += __shfl_xor_sync(0xffffffffu, d, 2);
                if (tig == 0) {
                    svp[wn * 128 + rl] = s;
                    dvp[wn * 128 + rl] = d;
                }
            }
        }
        __syncthreads();

        // ---------------- attention: 2 heads of this half ----------------
#pragma unroll 1
        for (int hl = 0; hl < 2; hl++) {
            const int gh = nh * 2 + hl;
            if (last && tid < 128) qbuf[tid] = 0.f;

#pragma unroll 1
            for (int rb = 0; rb < 2; rb++) {
                // softmax: 64 rows, 4 per warp
#pragma unroll
                for (int r = 0; r < 4; r++) {
                    int il = warp * 4 + r;
                    int ig = rb * 64 + il;
                    float di = dvp[hl * 256 + ig] + dvp[hl * 256 + 128 + ig];
                    float v[4];
                    float mx = -1e30f;
#pragma unroll
                    for (int q = 0; q < 4; q++) {
                        int j = lane + q * 32;
                        float sj = svp[hl * 256 + j] + svp[hl * 256 + 128 + j];
                        float a = sj + di;
                        a = (a >= 0.f) ? a : 0.2f * a;
                        v[q] = a;
                        mx = fmaxf(mx, a);
                    }
#pragma unroll
                    for (int off = 16; off; off >>= 1)
                        mx = fmaxf(mx, __shfl_xor_sync(0xffffffffu, mx, off));
                    float sum = 0.f;
#pragma unroll
                    for (int q = 0; q < 4; q++) {
                        v[q] = __expf(v[q] - mx);
                        sum += v[q];
                    }
#pragma unroll
                    for (int off = 16; off; off >>= 1)
                        sum += __shfl_xor_sync(0xffffffffu, sum, off);
                    float inv = 1.0f / sum;
#pragma unroll
                    for (int q = 0; q < 4; q++)
                        Pu[il * PSTR + lane + q * 32] = tf32r(v[q] * inv);
                }
                __syncthreads();

                if (!last) {
                    // OUT block(64x64) = P(64x128) @ Ht(h)^T; warp: 16x16 tile
                    float a2[2][4];
#pragma unroll
                    for (int nt = 0; nt < 2; nt++)
#pragma unroll
                        for (int c = 0; c < 4; c++) a2[nt][c] = 0.f;
#pragma unroll
                    for (int kk = 0; kk < 16; kk++) {
                        uint32_t a[4];
                        int r = (wm * 16 + gid) * PSTR + kk * 8 + tig;
                        a[0] = Pu[r];
                        a[1] = Pu[r + 8 * PSTR];
                        a[2] = Pu[r + 4];
                        a[3] = Pu[r + 8 * PSTR + 4];
                        uint32_t bf[2][2];
#pragma unroll
                        for (int nt = 0; nt < 2; nt++) {
                            int rr = (hl * 64 + wn * 16 + nt * 8 + gid) * PSTR
                                     + kk * 8 + tig;
                            bf[nt][0] = Htu[rr];
                            bf[nt][1] = Htu[rr + 4];
                        }
#pragma unroll
                        for (int nt = 0; nt < 2; nt++)
                            mma_tf32(a2[nt][0], a2[nt][1], a2[nt][2], a2[nt][3],
                                     a[0], a[1], a[2], a[3],
                                     bf[nt][0], bf[nt][1]);
                    }
#pragma unroll
                    for (int h2 = 0; h2 < 2; h2++)
#pragma unroll
                        for (int nt = 0; nt < 2; nt++) {
                            int row = rb * 64 + wm * 16 + gid + 8 * h2;
                            int col = wn * 16 + nt * 8 + tig * 2;
                            float* o = X + ((size_t)m0 + row) * 256 + gh * 64;
                            float2 rv = make_float2(
                                a2[nt][h2 * 2]     + biass[gh * 64 + col],
                                a2[nt][h2 * 2 + 1] + biass[gh * 64 + col + 1]);
                            *(float2*)&o[col] = rv;
                        }
                    __syncthreads();
                } else {
                    // column-sum accumulation: q_j += sum_i P[i][j]
                    if (tid < 128) {
                        float qs = 0.f;
#pragma unroll 8
                        for (int i = 0; i < 64; i++)
                            qs += __uint_as_float(Pu[i * PSTR + tid]);
                        qbuf[tid] += qs;
                    }
                    __syncthreads();
                }
            } // rb

            if (last) {
                // out[c] = sum_j q_j * Ht[h][c][j]  (+ 128*bias)
                int c = tid >> 3, t8 = tid & 7;
                float a3 = 0.f;
#pragma unroll 4
                for (int jj = 0; jj < 16; jj++) {
                    int j = t8 * 16 + jj;
                    a3 += qbuf[j] *
                          __uint_as_float(Htu[(hl * 64 + c) * PSTR + j]);
                }
                a3 += __shfl_xor_sync(0xffffffffu, a3, 1);
                a3 += __shfl_xor_sync(0xffffffffu, a3, 2);
                a3 += __shfl_xor_sync(0xffffffffu, a3, 4);
                if (t8 == 0)
                    out_final[(size_t)b * 256 + gh * 64 + c] =
                        a3 + 128.f * biass[gh * 64 + c];
                __syncthreads();
            }
        } // hl
    } // nh
}

// ---------------------------------------------------------------------------
extern "C" void kernel_launch(void* const* d_in, const int* in_sizes, int n_in,
                              void* d_out, int out_size)
{
    const float* x = (const float*)d_in[0];
    const float* W[3]    = {(const float*)d_in[2], (const float*)d_in[6],  (const float*)d_in[10]};
    const float* asv[3]  = {(const float*)d_in[3], (const float*)d_in[7],  (const float*)d_in[11]};
    const float* adv[3]  = {(const float*)d_in[4], (const float*)d_in[8],  (const float*)d_in[12]};
    const float* bias[3] = {(const float*)d_in[5], (const float*)d_in[9],  (const float*)d_in[13]};

    float *pX, *pY, *pWt;
    cudaGetSymbolAddress((void**)&pX, g_X);
    cudaGetSymbolAddress((void**)&pY, g_Y);
    cudaGetSymbolAddress((void**)&pWt, g_Wt);

    cudaFuncSetAttribute(layer_kernel,
                         cudaFuncAttributeMaxDynamicSharedMemorySize, LAYER_SMEM);

    transpose_all_kernel<<<640, 256>>>(W[0], W[1], W[2], pWt);

    // Ping-pong: x -> g_X -> g_Y -> d_out (A and X never alias)
    const float* in_buf[3]  = {x,  pX, pY};
    float*       out_buf[3] = {pX, pY, nullptr};

    for (int l = 0; l < 3; l++) {
        const int K = (l == 0) ? 128 : 256;
        const float* Wtl = pWt + (size_t)l * 65536;
        layer_kernel<<<512, 512, LAYER_SMEM>>>(
            in_buf[l], Wtl, asv[l], adv[l], bias[l],
            out_buf[l], (float*)d_out, K, l == 2);
    }
}

// round 7
// speedup vs baseline: 2.6591x; 1.0327x over previous
#include <cuda_runtime.h>
#include <cstdint>
#include <math.h>

#define B_GRAPHS 512
#define N_NODES  128
#define F_OUT    256
#define HEADS    4
#define HID      64
#define M_TOT    (B_GRAPHS * N_NODES)   // 65536

__device__ float g_X[(size_t)M_TOT * F_OUT];   // layer-0 output (tf32-rounded)
__device__ float g_Y[(size_t)M_TOT * F_OUT];   // xr (rounded input) / layer-1 output
__device__ float g_Wt[3][256 * 256];           // transposed weights [n][k], tf32

// ---------------------------------------------------------------------------
#define CP_ASYNC16(dst, src) \
    asm volatile("cp.async.cg.shared.global [%0], [%1], 16;" \
        :: "r"((uint32_t)(dst)), "l"(src) : "memory")
#define CP_COMMIT() asm volatile("cp.async.commit_group;" ::: "memory")
#define CP_WAIT1()  asm volatile("cp.async.wait_group 1;" ::: "memory")
#define CP_WAIT0()  asm volatile("cp.async.wait_group 0;" ::: "memory")

__device__ __forceinline__ uint32_t smem_to_u32(const void* p) {
    uint32_t a;
    asm("{ .reg .u64 t; cvta.to.shared.u64 t, %1; cvt.u32.u64 %0, t; }"
        : "=r"(a) : "l"(p));
    return a;
}

__device__ __forceinline__ uint32_t tf32r(float f) {
    uint32_t u;
    asm("cvt.rna.tf32.f32 %0, %1;" : "=r"(u) : "f"(f));
    return u;
}

__device__ __forceinline__ void ldsm_x4(
    uint32_t& r0, uint32_t& r1, uint32_t& r2, uint32_t& r3, uint32_t addr)
{
    asm volatile("ldmatrix.sync.aligned.m8n8.x4.shared.b16 {%0,%1,%2,%3}, [%4];"
        : "=r"(r0), "=r"(r1), "=r"(r2), "=r"(r3) : "r"(addr));
}

__device__ __forceinline__ void mma_tf32(
    float& d0, float& d1, float& d2, float& d3,
    uint32_t a0, uint32_t a1, uint32_t a2, uint32_t a3,
    uint32_t b0, uint32_t b1)
{
    asm volatile(
        "mma.sync.aligned.m16n8k8.row.col.f32.tf32.tf32.f32 "
        "{%0,%1,%2,%3}, {%4,%5,%6,%7}, {%8,%9}, {%0,%1,%2,%3};"
        : "+f"(d0), "+f"(d1), "+f"(d2), "+f"(d3)
        : "r"(a0), "r"(a1), "r"(a2), "r"(a3), "r"(b0), "r"(b1));
}

// ---------------------------------------------------------------------------
// Pre-round layer-0 input to tf32 (so the GEMM mainloop needs no cvt).
// ---------------------------------------------------------------------------
__global__ __launch_bounds__(256) void round_x_kernel(
    const float* __restrict__ x, float* __restrict__ xr)
{
    int t = blockIdx.x * 256 + threadIdx.x;       // x is 65536*128 = 2^23 elems
    float4 v = ((const float4*)x)[t];
    uint4 o = make_uint4(tf32r(v.x), tf32r(v.y), tf32r(v.z), tf32r(v.w));
    ((uint4*)xr)[t] = o;
}

// ---------------------------------------------------------------------------
// Transpose all three weight matrices (tf32-rounded).
// ---------------------------------------------------------------------------
__global__ __launch_bounds__(256) void transpose_all_kernel(
    const float* __restrict__ W0, const float* __restrict__ W1,
    const float* __restrict__ W2, float* __restrict__ Wt)
{
    int t = blockIdx.x * 256 + threadIdx.x;
    uint32_t* o = (uint32_t*)Wt;
    if (t < 128 * 256) {
        int k = t >> 8, n = t & 255;
        o[(size_t)n * 128 + k] = tf32r(W0[t]);
    } else if (t < 128 * 256 + 256 * 256) {
        int t2 = t - 128 * 256;
        int k = t2 >> 8, n = t2 & 255;
        o[65536 + (size_t)n * 256 + k] = tf32r(W1[t2]);
    } else {
        int t3 = t - 128 * 256 - 256 * 256;
        int k = t3 >> 8, n = t3 & 255;
        o[131072 + (size_t)n * 256 + k] = tf32r(W2[t3]);
    }
}

// ===========================================================================
// Fused layer kernel, 2 CTAs/SM, 512 threads. ldmatrix fragment loads.
// A and X must be distinct buffers (second N-half re-reads A).
// ===========================================================================
#define PSTR 132
#define OFF_SVP  3072
#define OFF_DVP  5120
#define OFF_Q    7168
#define OFF_U    7680
#define AS_STG   18432                 // 128 rows * 144B
#define OFF_HT2  0                     // Ht [128][132] f32 = 67584
#define OFF_PB   67584                 // P  [64][132]  f32 = 33792
#define U_SIZE   101376
#define LAYER_SMEM (OFF_U + U_SIZE)    // 109056 -> 2 CTAs/SM

__global__ __launch_bounds__(512, 2) void layer_kernel(
    const float* __restrict__ A, const float* __restrict__ Wt,
    const float* __restrict__ att_src, const float* __restrict__ att_dst,
    const float* __restrict__ bias_g,
    float* __restrict__ X, float* __restrict__ out_final,
    int K, int last)
{
    extern __shared__ char sm[];
    uint32_t sb = smem_to_u32(sm);
    float* atts  = (float*)(sm);
    float* attd  = (float*)(sm + 1024);
    float* biass = (float*)(sm + 2048);
    float* svp   = (float*)(sm + OFF_SVP);
    float* dvp   = (float*)(sm + OFF_DVP);
    float* qbuf  = (float*)(sm + OFF_Q);
    uint32_t* Htu = (uint32_t*)(sm + OFF_U + OFF_HT2);
    uint32_t* Pu  = (uint32_t*)(sm + OFF_U + OFF_PB);

    const int tid = threadIdx.x;
    const int warp = tid >> 5, lane = tid & 31;
    const int gid = lane >> 2, tig = lane & 3;
    const int wm = warp & 3, wn = warp >> 2;
    const int b = blockIdx.x, m0 = b * 128;
    const int t4 = lane >> 3, r8 = lane & 7;

    if (tid < 256) {
        atts[tid]  = att_src[tid];
        attd[tid]  = att_dst[tid];
        biass[tid] = bias_g[tid];
    }

    // ldmatrix per-lane byte offsets (within a stage / the U buffers)
    // GEMM A quadrants: t4: 0:(r+0,k+0) 1:(r+8,k+0) 2:(r+0,k+4) 3:(r+8,k+4)
    uint32_t aoff[2], boff[2];
#pragma unroll
    for (int mt = 0; mt < 2; mt++)
        aoff[mt] = (uint32_t)((wm * 32 + mt * 16 + (t4 & 1) * 8 + r8) * 144
                              + (t4 >> 1) * 16);
    // GEMM B pairs: tiles 0:(nt0,k0) 1:(nt0,k4) 2:(nt1,k0) 3:(nt1,k4)
#pragma unroll
    for (int pr = 0; pr < 2; pr++)
        boff[pr] = (uint32_t)((wn * 32 + pr * 16 + (t4 >> 1) * 8 + r8) * 144
                              + (t4 & 1) * 16);
    // attention: P (A-frag, 16 rows), Ht (B-frag, 16 n-rows)
    const uint32_t poff = (uint32_t)((wm * 16 + (t4 & 1) * 8 + r8) * 528
                                     + (t4 >> 1) * 16);
    const uint32_t hoff = (uint32_t)((wn * 16 + (t4 >> 1) * 8 + r8) * 528
                                     + (t4 & 1) * 16);

    const int NC = K >> 5;

#pragma unroll 1
    for (int nh = 0; nh < 2; nh++) {
        // ---------------- GEMM half: 128 x 128 ----------------
        float acc[2][4][4];
#pragma unroll
        for (int mt = 0; mt < 2; mt++)
#pragma unroll
            for (int nt = 0; nt < 4; nt++)
#pragma unroll
                for (int c = 0; c < 4; c++) acc[mt][nt][c] = 0.f;

        auto load_chunk = [&](int k0, int stage) {
            uint32_t ab = sb + OFF_U + stage * AS_STG;
            uint32_t bb = sb + OFF_U + 2 * AS_STG + stage * AS_STG;
#pragma unroll
            for (int i = 0; i < 2; i++) {
                int g = tid + i * 512;
                int row = g >> 3, c = g & 7;
                CP_ASYNC16(ab + row * 144 + c * 16,
                           A + (size_t)(m0 + row) * K + k0 + c * 4);
            }
#pragma unroll
            for (int i = 0; i < 2; i++) {
                int g = tid + i * 512;
                int row = g >> 3, c = g & 7;
                CP_ASYNC16(bb + row * 144 + c * 16,
                           Wt + (size_t)(nh * 128 + row) * K + k0 + c * 4);
            }
        };

        load_chunk(0, 0);
        CP_COMMIT();

        for (int c = 0; c < NC; c++) {
            if (c + 1 < NC) {
                load_chunk((c + 1) << 5, (c + 1) & 1);
                CP_COMMIT();
                CP_WAIT1();
            } else {
                CP_WAIT0();
            }
            __syncthreads();

            uint32_t as_b = sb + OFF_U + (c & 1) * AS_STG;
            uint32_t bs_b = sb + OFF_U + 2 * AS_STG + (c & 1) * AS_STG;
#pragma unroll
            for (int kk = 0; kk < 4; kk++) {
                uint32_t a[2][4];
#pragma unroll
                for (int mt = 0; mt < 2; mt++)
                    ldsm_x4(a[mt][0], a[mt][1], a[mt][2], a[mt][3],
                            as_b + aoff[mt] + kk * 32);
                uint32_t bf[4][2];
#pragma unroll
                for (int pr = 0; pr < 2; pr++)
                    ldsm_x4(bf[pr * 2][0], bf[pr * 2][1],
                            bf[pr * 2 + 1][0], bf[pr * 2 + 1][1],
                            bs_b + boff[pr] + kk * 32);
#pragma unroll
                for (int mt = 0; mt < 2; mt++)
#pragma unroll
                    for (int nt = 0; nt < 4; nt++)
                        mma_tf32(acc[mt][nt][0], acc[mt][nt][1],
                                 acc[mt][nt][2], acc[mt][nt][3],
                                 a[mt][0], a[mt][1], a[mt][2], a[mt][3],
                                 bf[nt][0], bf[nt][1]);
            }
            __syncthreads();
        }

        // ---------------- epilogue: Ht + score partials ----------------
        const int hl_w = wn >> 1;
#pragma unroll
        for (int mt = 0; mt < 2; mt++) {
#pragma unroll
            for (int h2 = 0; h2 < 2; h2++) {
                int rl = wm * 32 + mt * 16 + gid + 8 * h2;
                float s = 0.f, d = 0.f;
#pragma unroll
                for (int nt = 0; nt < 4; nt++) {
                    int cl = (wn & 1) * 32 + nt * 8 + tig * 2;
                    int gc = nh * 128 + wn * 32 + nt * 8 + tig * 2;
                    float v0 = acc[mt][nt][h2 * 2], v1 = acc[mt][nt][h2 * 2 + 1];
                    s = fmaf(v0, atts[gc], s);  s = fmaf(v1, atts[gc + 1], s);
                    d = fmaf(v0, attd[gc], d);  d = fmaf(v1, attd[gc + 1], d);
                    Htu[(hl_w * 64 + cl) * PSTR + rl]     = tf32r(v0);
                    Htu[(hl_w * 64 + cl + 1) * PSTR + rl] = tf32r(v1);
                }
                s += __shfl_xor_sync(0xffffffffu, s, 1);
                s += __shfl_xor_sync(0xffffffffu, s, 2);
                d += __shfl_xor_sync(0xffffffffu, d, 1);
                d += __shfl_xor_sync(0xffffffffu, d, 2);
                if (tig == 0) {
                    svp[wn * 128 + rl] = s;
                    dvp[wn * 128 + rl] = d;
                }
            }
        }
        __syncthreads();

        // ---------------- attention: 2 heads of this half ----------------
#pragma unroll 1
        for (int hl = 0; hl < 2; hl++) {
            const int gh = nh * 2 + hl;
            const uint32_t ht_b = sb + OFF_U + OFF_HT2 + hl * 33792;
            if (last && tid < 128) qbuf[tid] = 0.f;

#pragma unroll 1
            for (int rb = 0; rb < 2; rb++) {
                // softmax: 64 rows, 4 per warp
#pragma unroll
                for (int r = 0; r < 4; r++) {
                    int il = warp * 4 + r;
                    int ig = rb * 64 + il;
                    float di = dvp[hl * 256 + ig] + dvp[hl * 256 + 128 + ig];
                    float v[4];
                    float mx = -1e30f;
#pragma unroll
                    for (int q = 0; q < 4; q++) {
                        int j = lane + q * 32;
                        float sj = svp[hl * 256 + j] + svp[hl * 256 + 128 + j];
                        float a = sj + di;
                        a = (a >= 0.f) ? a : 0.2f * a;
                        v[q] = a;
                        mx = fmaxf(mx, a);
                    }
#pragma unroll
                    for (int off = 16; off; off >>= 1)
                        mx = fmaxf(mx, __shfl_xor_sync(0xffffffffu, mx, off));
                    float sum = 0.f;
#pragma unroll
                    for (int q = 0; q < 4; q++) {
                        v[q] = __expf(v[q] - mx);
                        sum += v[q];
                    }
#pragma unroll
                    for (int off = 16; off; off >>= 1)
                        sum += __shfl_xor_sync(0xffffffffu, sum, off);
                    float inv = 1.0f / sum;
#pragma unroll
                    for (int q = 0; q < 4; q++)
                        Pu[il * PSTR + lane + q * 32] = tf32r(v[q] * inv);
                }
                __syncthreads();

                if (!last) {
                    float a2[2][4];
#pragma unroll
                    for (int nt = 0; nt < 2; nt++)
#pragma unroll
                        for (int c = 0; c < 4; c++) a2[nt][c] = 0.f;
                    const uint32_t p_b = sb + OFF_U + OFF_PB;
#pragma unroll
                    for (int kk = 0; kk < 16; kk++) {
                        uint32_t a[4];
                        ldsm_x4(a[0], a[1], a[2], a[3], p_b + poff + kk * 32);
                        uint32_t bf[2][2];
                        ldsm_x4(bf[0][0], bf[0][1], bf[1][0], bf[1][1],
                                ht_b + hoff + kk * 32);
#pragma unroll
                        for (int nt = 0; nt < 2; nt++)
                            mma_tf32(a2[nt][0], a2[nt][1], a2[nt][2], a2[nt][3],
                                     a[0], a[1], a[2], a[3],
                                     bf[nt][0], bf[nt][1]);
                    }
#pragma unroll
                    for (int h2 = 0; h2 < 2; h2++)
#pragma unroll
                        for (int nt = 0; nt < 2; nt++) {
                            int row = rb * 64 + wm * 16 + gid + 8 * h2;
                            int col = wn * 16 + nt * 8 + tig * 2;
                            float* o = X + ((size_t)m0 + row) * 256 + gh * 64;
                            // store tf32-rounded: next layer consumes directly
                            uint32_t u0 = tf32r(a2[nt][h2 * 2]
                                                + biass[gh * 64 + col]);
                            uint32_t u1 = tf32r(a2[nt][h2 * 2 + 1]
                                                + biass[gh * 64 + col + 1]);
                            float2 rv = make_float2(__uint_as_float(u0),
                                                    __uint_as_float(u1));
                            *(float2*)&o[col] = rv;
                        }
                    __syncthreads();
                } else {
                    if (tid < 128) {
                        float qs = 0.f;
#pragma unroll 8
                        for (int i = 0; i < 64; i++)
                            qs += __uint_as_float(Pu[i * PSTR + tid]);
                        qbuf[tid] += qs;
                    }
                    __syncthreads();
                }
            } // rb

            if (last) {
                int c = tid >> 3, t8 = tid & 7;
                float a3 = 0.f;
#pragma unroll 4
                for (int jj = 0; jj < 16; jj++) {
                    int j = t8 * 16 + jj;
                    a3 += qbuf[j] *
                          __uint_as_float(Htu[(hl * 64 + c) * PSTR + j]);
                }
                a3 += __shfl_xor_sync(0xffffffffu, a3, 1);
                a3 += __shfl_xor_sync(0xffffffffu, a3, 2);
                a3 += __shfl_xor_sync(0xffffffffu, a3, 4);
                if (t8 == 0)
                    out_final[(size_t)b * 256 + gh * 64 + c] =
                        a3 + 128.f * biass[gh * 64 + c];
                __syncthreads();
            }
        } // hl
    } // nh
}

// ---------------------------------------------------------------------------
extern "C" void kernel_launch(void* const* d_in, const int* in_sizes, int n_in,
                              void* d_out, int out_size)
{
    const float* x = (const float*)d_in[0];
    const float* W[3]    = {(const float*)d_in[2], (const float*)d_in[6],  (const float*)d_in[10]};
    const float* asv[3]  = {(const float*)d_in[3], (const float*)d_in[7],  (const float*)d_in[11]};
    const float* adv[3]  = {(const float*)d_in[4], (const float*)d_in[8],  (const float*)d_in[12]};
    const float* bias[3] = {(const float*)d_in[5], (const float*)d_in[9],  (const float*)d_in[13]};

    float *pX, *pY, *pWt;
    cudaGetSymbolAddress((void**)&pX, g_X);
    cudaGetSymbolAddress((void**)&pY, g_Y);
    cudaGetSymbolAddress((void**)&pWt, g_Wt);

    cudaFuncSetAttribute(layer_kernel,
                         cudaFuncAttributeMaxDynamicSharedMemorySize, LAYER_SMEM);

    transpose_all_kernel<<<640, 256>>>(W[0], W[1], W[2], pWt);
    round_x_kernel<<<8192, 256>>>(x, pY);     // xr -> g_Y (dead after layer 0)

    // layer 0: g_Y(xr) -> g_X ; layer 1: g_X -> g_Y ; layer 2: g_Y -> d_out
    const float* in_buf[3]  = {pY, pX, pY};
    float*       out_buf[3] = {pX, pY, nullptr};

    for (int l = 0; l < 3; l++) {
        const int K = (l == 0) ? 128 : 256;
        const float* Wtl = pWt + (size_t)l * 65536;
        layer_kernel<<<512, 512, LAYER_SMEM>>>(
            in_buf[l], Wtl, asv[l], adv[l], bias[l],
            out_buf[l], (float*)d_out, K, l == 2);
    }
}